// round 15
// baseline (speedup 1.0000x reference)
#include <cuda_runtime.h>
#include <cstdint>

static constexpr int D      = 128;
static constexpr int K      = 8;
static constexpr int WARPS  = 8;      // per block (256 threads)
static constexpr int ITERS  = 8;      // 16 pairs/warp -> 782 blocks (single wave @6/SM)
static constexpr int PPI    = 2;      // pairs per iteration
static constexpr int STAGE_FLOATS = PPI * 2 * D;      // 512 floats = 2048 B
static constexpr int STAGE_BYTES  = STAGE_FLOATS * 4; // 2048
static constexpr int ROW_BYTES    = D * 4;            // 512

__global__ void spl_zero_kernel(float* out) { *out = 0.0f; }

__device__ __forceinline__ void cpa16(uint32_t dst, const float* src) {
    asm volatile("cp.async.cg.shared.global [%0], [%1], 16;\n" :: "r"(dst), "l"(src));
}
__device__ __forceinline__ void cpa_commit() {
    asm volatile("cp.async.commit_group;\n" ::: "memory");
}
__device__ __forceinline__ void cpa_wait1() {
    asm volatile("cp.async.wait_group 1;\n" ::: "memory");
}

// Per-warp pipelined work. TAIL=false: all 16 pairs valid, no guards/clamps.
template<bool TAIL>
__device__ __forceinline__ float warp_work(
    const float* __restrict__ emb,
    const int*   __restrict__ pair_ids,
    const int*   __restrict__ dims,
    float* mybuf, unsigned* mymarks,
    int warp_global, int lane, int n_pairs)
{
    const unsigned FULL = 0xFFFFFFFFu;
    const int  base    = warp_global * (PPI * ITERS);
    const int  wgI     = warp_global * ITERS;
    uint32_t   sb      = (uint32_t)__cvta_generic_to_shared(mybuf) + lane * 16;
    const int  id4_max = (n_pairs >> 1) - 1;
    const long dim_max = (long)n_pairs * K - 1;

    auto load_ids = [&](int i) -> int4 {
        int idx = wgI + i;
        if (TAIL && idx > id4_max) idx = id4_max;
        return __ldg((const int4*)pair_ids + idx);
    };
    auto load_dim = [&](int i) -> int {
        long idx = (long)(base + PPI * i) * K + lane;   // lanes 0..15 used
        if (TAIL && idx > dim_max) idx = dim_max;
        return __ldg(dims + idx);
    };
    auto valid = [&](int i, int sub) {
        return TAIL ? (base + PPI * i + sub < n_pairs) : true;
    };
    auto issue_stage = [&](int s, int4 pr, bool v0, bool v1) {
        uint32_t dst = sb + (uint32_t)s * STAGE_BYTES;
        if (v0) {
            cpa16(dst,                 emb + (size_t)pr.x * D + lane * 4);
            cpa16(dst + ROW_BYTES,     emb + (size_t)pr.y * D + lane * 4);
        }
        if (v1) {
            cpa16(dst + 2 * ROW_BYTES, emb + (size_t)pr.z * D + lane * 4);
            cpa16(dst + 3 * ROW_BYTES, emb + (size_t)pr.w * D + lane * 4);
        }
    };

    // ---- prologue ----
    int4 id_q[2];
    int  dim_q[4];
    id_q[0]  = load_ids(0);
    dim_q[0] = load_dim(0);
    issue_stage(0, id_q[0], valid(0, 0), valid(0, 1));
    cpa_commit();
    id_q[1]  = load_ids(1);
    dim_q[1] = load_dim(1);

    float c = 0.0f;
    #pragma unroll
    for (int i = 0; i < ITERS; i++) {
        // 1) issue prefetch for iter i+1 (slot last read in iter i-1, fenced below)
        if (i + 1 < ITERS)
            issue_stage((i + 1) & 1, id_q[(i + 1) & 1], valid(i + 1, 0), valid(i + 1, 1));
        cpa_commit();   // uniform group accounting

        // 2) start index loads for iter i+2
        if (i + 2 < ITERS) {
            id_q[i & 1]        = load_ids(i + 2);
            dim_q[(i + 2) & 3] = load_dim(i + 2);
        }

        const bool v0 = valid(i, 0);
        const bool v1 = valid(i, 1);
        const int  mydim = dim_q[i & 3];
        const bool pol   = (lane < 8) ? v0 : (lane < 16 && v1);

        // 3) marks + distinct counts: depends only on dims -> executed BEFORE
        //    the stage wait, fully overlapped with the in-flight cp.async.
        mymarks[lane]      = 0u;
        mymarks[lane + 32] = 0u;
        __syncwarp();
        if (pol)
            ((unsigned char*)mymarks)[((lane >> 3) << 7) + mydim] = 1;
        __syncwarp();
        unsigned w0 = mymarks[lane];
        unsigned w1 = mymarks[lane + 32];
        unsigned d0 = __reduce_add_sync(FULL, (w0 * 0x01010101u) >> 24);
        unsigned d1 = __reduce_add_sync(FULL, (w1 * 0x01010101u) >> 24);
        float invk0 = __fdividef(0.5f, (float)(D - (int)d0));
        float invk1 = __fdividef(0.5f, (float)(D - (int)d1));

        // 4) wait for stage i, make cp.async writes cross-lane visible
        cpa_wait1();
        __syncwarp();

        const float* buf = mybuf + (i & 1) * STAGE_FLOATS;

        // 5) data-dependent phase only: gathers, rows, FMAs, polarity
        float g1 = 0.0f, g2 = 0.0f;
        if (pol) {
            int rs = (lane >> 3) * 256;
            g1 = buf[rs + mydim];
            g2 = buf[rs + 128 + mydim];
        }

        if (v0) {
            float4 A = ((const float4*)buf)[lane];
            float4 B = ((const float4*)(buf + 128))[lane];
            float dx = A.x - B.x, dy = A.y - B.y, dz = A.z - B.z, dw = A.w - B.w;
            float kept = 0.0f;
            if (!(w0 & 0x000000FFu)) kept = fmaf(dx, dx, kept);
            if (!(w0 & 0x0000FF00u)) kept = fmaf(dy, dy, kept);
            if (!(w0 & 0x00FF0000u)) kept = fmaf(dz, dz, kept);
            if (!(w0 & 0xFF000000u)) kept = fmaf(dw, dw, kept);
            c = fmaf(kept, invk0, c);
        }
        if (v1) {
            float4 A = ((const float4*)(buf + 256))[lane];
            float4 B = ((const float4*)(buf + 384))[lane];
            float dx = A.x - B.x, dy = A.y - B.y, dz = A.z - B.z, dw = A.w - B.w;
            float kept = 0.0f;
            if (!(w1 & 0x000000FFu)) kept = fmaf(dx, dx, kept);
            if (!(w1 & 0x0000FF00u)) kept = fmaf(dy, dy, kept);
            if (!(w1 & 0x00FF0000u)) kept = fmaf(dz, dz, kept);
            if (!(w1 & 0xFF000000u)) kept = fmaf(dw, dw, kept);
            c = fmaf(kept, invk1, c);
        }

        if (pol) {
            // polarity (duplicates counted; sign_prod==0 iff either value is +-0)
            float sm  = fabsf(g1) + fabsf(g2);
            bool zero = (g1 == 0.0f) || (g2 == 0.0f);
            bool opp  = ((__float_as_int(g1) ^ __float_as_int(g2)) < 0);
            c += zero ? 0.1f : (opp ? -0.5f * sm : sm);
        }
        __syncwarp();   // stage-reuse + marks-reuse safety before next iteration
    }
    return c;
}

__global__ __launch_bounds__(256, 6) void spl_loss_kernel(
    const float* __restrict__ emb,
    const int*   __restrict__ pair_ids,
    const int*   __restrict__ dims,
    float*       __restrict__ out,
    int n_pairs, float inv_p)
{
    const unsigned FULL = 0xFFFFFFFFu;
    const int lane = threadIdx.x & 31;
    const int wid  = threadIdx.x >> 5;

    __shared__ float    rows[WARPS][2 * STAGE_FLOATS];   // 32 KB double buffer
    __shared__ unsigned marks[WARPS][64];                // 2 KB
    __shared__ float    warp_sums[WARPS];

    const int warp_global = blockIdx.x * WARPS + wid;
    const int base        = warp_global * (PPI * ITERS);

    float c = 0.0f;
    if (base + PPI * ITERS <= n_pairs) {
        c = warp_work<false>(emb, pair_ids, dims, rows[wid], marks[wid],
                             warp_global, lane, n_pairs);
    } else if (base < n_pairs) {
        c = warp_work<true>(emb, pair_ids, dims, rows[wid], marks[wid],
                            warp_global, lane, n_pairs);
    }

    // ---- warp butterfly + block reduce + one atomic per block ----
    #pragma unroll
    for (int off = 16; off > 0; off >>= 1)
        c += __shfl_xor_sync(FULL, c, off);
    if (lane == 0) warp_sums[wid] = c;
    __syncthreads();
    if (threadIdx.x == 0) {
        float s = 0.0f;
        #pragma unroll
        for (int v = 0; v < WARPS; v++) s += warp_sums[v];
        atomicAdd(out, s * inv_p);
    }
}

extern "C" void kernel_launch(void* const* d_in, const int* in_sizes, int n_in,
                              void* d_out, int out_size)
{
    const float* emb      = (const float*)d_in[0];  // (VOCAB, 128) f32
    const int*   pair_ids = (const int*)  d_in[1];  // (P, 2) i32
    const int*   dims     = (const int*)  d_in[2];  // (P, 8) i32
    float*       out      = (float*)d_out;          // scalar f32

    int n_pairs = in_sizes[1] / 2;
    spl_zero_kernel<<<1, 1>>>(out);

    // 16 pairs/warp -> 782 blocks (P=100000); 6 blocks/SM x 148 SMs = 888
    // resident capacity -> single wave with ~5.3 blocks/SM (more resident
    // warps than R14's 695-block launch).
    int pairs_per_warp = PPI * ITERS;                        // 16
    int warps_needed   = (n_pairs + pairs_per_warp - 1) / pairs_per_warp;
    int blocks         = (warps_needed + WARPS - 1) / WARPS;
    spl_loss_kernel<<<blocks, 256>>>(emb, pair_ids, dims, out,
                                     n_pairs, 1.0f / (float)n_pairs);
}

// round 16
// speedup vs baseline: 1.0057x; 1.0057x over previous
#include <cuda_runtime.h>
#include <cstdint>

static constexpr int D      = 128;
static constexpr int K      = 8;
static constexpr int WARPS  = 8;      // per block (256 threads)
static constexpr int ITERS  = 9;      // 18 pairs/warp -> 695 blocks (single wave @6/SM)
static constexpr int PPI    = 2;      // pairs per iteration
static constexpr int STAGE_FLOATS = PPI * 2 * D;      // 512 floats = 2048 B
static constexpr int STAGE_BYTES  = STAGE_FLOATS * 4; // 2048
static constexpr int ROW_BYTES    = D * 4;            // 512

// Cross-launch scratch for the single-kernel final reduction.
// Zero at load; the finishing block resets both after consuming them,
// so every graph replay sees the same initial state (deterministic).
__device__ float    g_scratch = 0.0f;
__device__ unsigned g_count   = 0u;

__device__ __forceinline__ void cpa16(uint32_t dst, const float* src) {
    asm volatile("cp.async.cg.shared.global [%0], [%1], 16;\n" :: "r"(dst), "l"(src));
}
__device__ __forceinline__ void cpa_commit() {
    asm volatile("cp.async.commit_group;\n" ::: "memory");
}
__device__ __forceinline__ void cpa_wait1() {
    asm volatile("cp.async.wait_group 1;\n" ::: "memory");
}

// Per-warp pipelined work. TAIL=false: all 18 pairs valid, no guards/clamps.
template<bool TAIL>
__device__ __forceinline__ float warp_work(
    const float* __restrict__ emb,
    const int*   __restrict__ pair_ids,
    const int*   __restrict__ dims,
    float* mybuf, unsigned* mymarks,
    int warp_global, int lane, int n_pairs)
{
    const unsigned FULL = 0xFFFFFFFFu;
    const int  base    = warp_global * (PPI * ITERS);
    const int  wgI     = warp_global * ITERS;
    uint32_t   sb      = (uint32_t)__cvta_generic_to_shared(mybuf) + lane * 16;
    const int  id4_max = (n_pairs >> 1) - 1;
    const long dim_max = (long)n_pairs * K - 1;

    auto load_ids = [&](int i) -> int4 {
        int idx = wgI + i;
        if (TAIL && idx > id4_max) idx = id4_max;
        return __ldg((const int4*)pair_ids + idx);
    };
    auto load_dim = [&](int i) -> int {
        long idx = (long)(base + PPI * i) * K + lane;   // lanes 0..15 used
        if (TAIL && idx > dim_max) idx = dim_max;
        return __ldg(dims + idx);
    };
    auto valid = [&](int i, int sub) {
        return TAIL ? (base + PPI * i + sub < n_pairs) : true;
    };
    auto issue_stage = [&](int s, int4 pr, bool v0, bool v1) {
        uint32_t dst = sb + (uint32_t)s * STAGE_BYTES;
        if (v0) {
            cpa16(dst,                 emb + (size_t)pr.x * D + lane * 4);
            cpa16(dst + ROW_BYTES,     emb + (size_t)pr.y * D + lane * 4);
        }
        if (v1) {
            cpa16(dst + 2 * ROW_BYTES, emb + (size_t)pr.z * D + lane * 4);
            cpa16(dst + 3 * ROW_BYTES, emb + (size_t)pr.w * D + lane * 4);
        }
    };

    // ---- prologue ----
    mymarks[lane]      = 0u;     // zero marks ONCE; iterations use unique tags
    mymarks[lane + 32] = 0u;
    __syncwarp();

    int4 id_q[2];
    int  dim_q[4];
    id_q[0]  = load_ids(0);
    dim_q[0] = load_dim(0);
    issue_stage(0, id_q[0], valid(0, 0), valid(0, 1));
    cpa_commit();
    id_q[1]  = load_ids(1);
    dim_q[1] = load_dim(1);

    float c = 0.0f;
    #pragma unroll
    for (int i = 0; i < ITERS; i++) {
        // 1) issue prefetch for iter i+1 (slot last read in iter i-1, fenced below)
        if (i + 1 < ITERS)
            issue_stage((i + 1) & 1, id_q[(i + 1) & 1], valid(i + 1, 0), valid(i + 1, 1));
        cpa_commit();   // uniform group accounting

        // 2) start index loads for iter i+2
        if (i + 2 < ITERS) {
            id_q[i & 1]        = load_ids(i + 2);
            dim_q[(i + 2) & 3] = load_dim(i + 2);
        }

        // 3) wait for stage i, make cp.async writes cross-lane visible
        cpa_wait1();
        __syncwarp();

        const float* buf = mybuf + (i & 1) * STAGE_FLOATS;
        const bool v0 = valid(i, 0);
        const bool v1 = valid(i, 1);
        const int  mydim = dim_q[i & 3];
        const bool pol   = (lane < 8) ? v0 : (lane < 16 && v1);

        // marks: tag-write (tag = i+1; stale bytes hold smaller tags, never match)
        const unsigned tag = (unsigned)(i + 1);
        if (pol)
            ((unsigned char*)mymarks)[((lane >> 3) << 7) + mydim] = (unsigned char)tag;
        __syncwarp();
        unsigned w0 = mymarks[lane];
        unsigned w1 = mymarks[lane + 32];

        // zero-byte detect on (w ^ tag4): bit 7 of each matching byte set
        const unsigned tag4 = tag * 0x01010101u;
        unsigned x0 = w0 ^ tag4;
        unsigned x1 = w1 ^ tag4;
        unsigned m0 = (x0 - 0x01010101u) & ~x0 & 0x80808080u;
        unsigned m1 = (x1 - 0x01010101u) & ~x1 & 0x80808080u;

        // distinct-dim counts, both pairs in ONE packed REDUX
        unsigned packed = (unsigned)__popc(m0) | ((unsigned)__popc(m1) << 16);
        unsigned r = __reduce_add_sync(FULL, packed);
        float invk0 = __fdividef(0.5f, (float)(D - (int)(r & 0xFFFFu)));
        float invk1 = __fdividef(0.5f, (float)(D - (int)(r >> 16)));

        // polarity gathers from smem rows
        float g1 = 0.0f, g2 = 0.0f;
        if (pol) {
            int rs = (lane >> 3) * 256;
            g1 = buf[rs + mydim];
            g2 = buf[rs + 128 + mydim];
        }

        if (v0) {
            float4 A = ((const float4*)buf)[lane];
            float4 B = ((const float4*)(buf + 128))[lane];
            float dx = A.x - B.x, dy = A.y - B.y, dz = A.z - B.z, dw = A.w - B.w;
            float kept = 0.0f;
            if (!(m0 & 0x00000080u)) kept = fmaf(dx, dx, kept);
            if (!(m0 & 0x00008000u)) kept = fmaf(dy, dy, kept);
            if (!(m0 & 0x00800000u)) kept = fmaf(dz, dz, kept);
            if (!(m0 & 0x80000000u)) kept = fmaf(dw, dw, kept);
            c = fmaf(kept, invk0, c);
        }
        if (v1) {
            float4 A = ((const float4*)(buf + 256))[lane];
            float4 B = ((const float4*)(buf + 384))[lane];
            float dx = A.x - B.x, dy = A.y - B.y, dz = A.z - B.z, dw = A.w - B.w;
            float kept = 0.0f;
            if (!(m1 & 0x00000080u)) kept = fmaf(dx, dx, kept);
            if (!(m1 & 0x00008000u)) kept = fmaf(dy, dy, kept);
            if (!(m1 & 0x00800000u)) kept = fmaf(dz, dz, kept);
            if (!(m1 & 0x80000000u)) kept = fmaf(dw, dw, kept);
            c = fmaf(kept, invk1, c);
        }

        if (pol) {
            // polarity (duplicates counted; sign_prod==0 iff either value is +-0)
            float sm  = fabsf(g1) + fabsf(g2);
            bool zero = (g1 == 0.0f) || (g2 == 0.0f);
            bool opp  = ((__float_as_int(g1) ^ __float_as_int(g2)) < 0);
            c += zero ? 0.1f : (opp ? -0.5f * sm : sm);
        }
        __syncwarp();   // stage-reuse + marks write/read ordering for next iter
    }
    return c;
}

__global__ __launch_bounds__(256, 6) void spl_loss_kernel(
    const float* __restrict__ emb,
    const int*   __restrict__ pair_ids,
    const int*   __restrict__ dims,
    float*       __restrict__ out,
    int n_pairs, float inv_p)
{
    const unsigned FULL = 0xFFFFFFFFu;
    const int lane = threadIdx.x & 31;
    const int wid  = threadIdx.x >> 5;

    __shared__ float    rows[WARPS][2 * STAGE_FLOATS];   // 32 KB double buffer
    __shared__ unsigned marks[WARPS][64];                // 2 KB
    __shared__ float    warp_sums[WARPS];

    const int warp_global = blockIdx.x * WARPS + wid;
    const int base        = warp_global * (PPI * ITERS);

    float c = 0.0f;
    if (base + PPI * ITERS <= n_pairs) {
        c = warp_work<false>(emb, pair_ids, dims, rows[wid], marks[wid],
                             warp_global, lane, n_pairs);
    } else if (base < n_pairs) {
        c = warp_work<true>(emb, pair_ids, dims, rows[wid], marks[wid],
                            warp_global, lane, n_pairs);
    }

    // ---- warp butterfly + block reduce ----
    #pragma unroll
    for (int off = 16; off > 0; off >>= 1)
        c += __shfl_xor_sync(FULL, c, off);
    if (lane == 0) warp_sums[wid] = c;
    __syncthreads();

    // ---- single-kernel finish: scratch accumulate + last-block writes out ----
    if (threadIdx.x == 0) {
        float s = 0.0f;
        #pragma unroll
        for (int v = 0; v < WARPS; v++) s += warp_sums[v];
        atomicAdd(&g_scratch, s);
        __threadfence();
        unsigned done = atomicAdd(&g_count, 1u);
        if (done == gridDim.x - 1) {
            // all blocks' scratch-adds are fenced before their count-inc,
            // and we observed all counts -> total is visible.
            float tot = *((volatile float*)&g_scratch);
            *out = tot * inv_p;
            g_scratch = 0.0f;    // reset for the next graph replay
            g_count   = 0u;
        }
    }
}

extern "C" void kernel_launch(void* const* d_in, const int* in_sizes, int n_in,
                              void* d_out, int out_size)
{
    const float* emb      = (const float*)d_in[0];  // (VOCAB, 128) f32
    const int*   pair_ids = (const int*)  d_in[1];  // (P, 2) i32
    const int*   dims     = (const int*)  d_in[2];  // (P, 8) i32
    float*       out      = (float*)d_out;          // scalar f32

    int n_pairs = in_sizes[1] / 2;

    // 18 pairs/warp -> 695 blocks (P=100000); single wave (proven R14 config).
    int pairs_per_warp = PPI * ITERS;                        // 18
    int warps_needed   = (n_pairs + pairs_per_warp - 1) / pairs_per_warp;
    int blocks         = (warps_needed + WARPS - 1) / WARPS;
    spl_loss_kernel<<<blocks, 256>>>(emb, pair_ids, dims, out,
                                     n_pairs, 1.0f / (float)n_pairs);
}